// round 5
// baseline (speedup 1.0000x reference)
#include <cuda_runtime.h>
#include <cuda_bf16.h>
#include <math.h>

#define KE       14.3996f
#define ALPHA    0.3f
#define CUTOFF   10.0f
#define NMOL     64
#define MAXA     100000
#define MAXK     1024
#define TWOPI    6.283185307179586f
#define SQA      0.5477225575051661f   /* sqrt(0.3) */

// -------- device scratch (no allocation allowed) --------
__device__ float  g_recip[NMOL][9];     // B[d][e] row-major: kv_e = sum_d g_d * B[d*3+e]
__device__ float  g_pref[NMOL];         // 2*pi / |det(cell)|
__device__ int    g_start[NMOL + 1];    // atom range per molecule (idx_m sorted)
__device__ int    g_halfk[MAXK];        // indices of half-space k vectors
__device__ int    g_nhalf;
__device__ float2 g_qmol[MAXA];         // {q, __int_as_float(mol)}

// =====================================================================
// Setup: zero out, per-molecule recip boxes, molecule offsets, half-k list,
//        packed (q, mol) array.   NOTE: indices are int32 (JAX x64 disabled).
// =====================================================================
__global__ __launch_bounds__(256) void setup_kernel(
    const float* __restrict__ q, const float* __restrict__ cell,
    const float* __restrict__ kvecs, const int* __restrict__ idx_m,
    int natoms, int nk, float* __restrict__ out)
{
    int tid = threadIdx.x;
    if (blockIdx.x == 0) {
        if (tid < NMOL) {
            // 3x3 inverse for cell m = tid
            const float* a = cell + 9 * tid;
            float a00 = a[0], a01 = a[1], a02 = a[2];
            float a10 = a[3], a11 = a[4], a12 = a[5];
            float a20 = a[6], a21 = a[7], a22 = a[8];
            float c00 = a11 * a22 - a12 * a21;
            float c01 = a02 * a21 - a01 * a22;
            float c02 = a01 * a12 - a02 * a11;
            float c10 = a12 * a20 - a10 * a22;
            float c11 = a00 * a22 - a02 * a20;
            float c12 = a02 * a10 - a00 * a12;
            float c20 = a10 * a21 - a11 * a20;
            float c21 = a01 * a20 - a00 * a21;
            float c22 = a00 * a11 - a01 * a10;
            float det = a00 * c00 + a01 * c10 + a02 * c20;
            float id = 1.0f / det;
            // inv[r][c]
            float i00 = c00 * id, i01 = c01 * id, i02 = c02 * id;
            float i10 = c10 * id, i11 = c11 * id, i12 = c12 * id;
            float i20 = c20 * id, i21 = c21 * id, i22 = c22 * id;
            // B[d*3+e] = 2*pi * inv[e][d]  (recip_box = 2*pi * inv(cell)^T)
            g_recip[tid][0] = TWOPI * i00;
            g_recip[tid][1] = TWOPI * i10;
            g_recip[tid][2] = TWOPI * i20;
            g_recip[tid][3] = TWOPI * i01;
            g_recip[tid][4] = TWOPI * i11;
            g_recip[tid][5] = TWOPI * i21;
            g_recip[tid][6] = TWOPI * i02;
            g_recip[tid][7] = TWOPI * i12;
            g_recip[tid][8] = TWOPI * i22;
            g_pref[tid] = TWOPI / fabsf(det);
            out[tid] = 0.0f;
        } else if (tid < 2 * NMOL + 1) {
            // lower_bound of m in sorted idx_m -> g_start[m]
            int m = tid - NMOL;
            int lo = 0, hi = natoms;
            while (lo < hi) {
                int mid = (lo + hi) >> 1;
                if (idx_m[mid] < m) lo = mid + 1; else hi = mid;
            }
            g_start[m] = lo;
        } else if (tid == 160) {
            // half-space k selection (sign-symmetric set; exactly one of {k,-k})
            int c = 0;
            for (int k = 0; k < nk && c < MAXK; k++) {
                float gx = kvecs[3 * k], gy = kvecs[3 * k + 1], gz = kvecs[3 * k + 2];
                bool sel = (gz > 0.0f) ||
                           (gz == 0.0f && gy > 0.0f) ||
                           (gz == 0.0f && gy == 0.0f && gx > 0.0f);
                if (sel) g_halfk[c++] = k;
            }
            g_nhalf = c;
        }
    }
    // pack (q, mol) for the real-space gather path
    for (int a = blockIdx.x * blockDim.x + tid; a < natoms; a += gridDim.x * blockDim.x) {
        int m = idx_m[a];
        g_qmol[a] = make_float2(q[a], __int_as_float(m));
    }
}

// =====================================================================
// Real space: grid-stride over pairs, shared per-molecule accumulators.
// =====================================================================
__global__ __launch_bounds__(256) void real_kernel(
    const float* __restrict__ Rij,
    const int* __restrict__ idx_i, const int* __restrict__ idx_j,
    const float* __restrict__ q, float* __restrict__ out, int npairs)
{
    __shared__ float acc[NMOL];
    int tid = threadIdx.x;
    if (tid < NMOL) acc[tid] = 0.0f;
    __syncthreads();

    const float frcut = erfcf(SQA * CUTOFF) / CUTOFF;
    const float cut2 = CUTOFF * CUTOFF;

    for (int p = blockIdx.x * blockDim.x + tid; p < npairs; p += gridDim.x * blockDim.x) {
        float x = Rij[3 * p], y = Rij[3 * p + 1], z = Rij[3 * p + 2];
        float d2 = x * x + y * y + z * z;
        if (d2 <= cut2) {
            int i = idx_i[p];
            int j = idx_j[p];
            float2 qm = __ldg(&g_qmol[i]);    // {q_i, mol bits} one 8B gather
            float qj = __ldg(&q[j]);
            float d = sqrtf(d2);
            float fr = erfcf(SQA * d) / d - frcut;
            float pot = qm.x * qj * fr;
            atomicAdd(&acc[__float_as_int(qm.y)], pot);
        }
    }
    __syncthreads();
    if (tid < NMOL) atomicAdd(&out[tid], 0.5f * KE * acc[tid]);
}

// =====================================================================
// Reciprocal space: block = (molecule, k-chunk), thread = one half-space k,
// loop over the molecule's atoms via shared float4 tiles. +- k symmetry => x2.
// Self-energy folded into blockIdx.y == 0 blocks.
// =====================================================================
#define RT 256

__device__ __forceinline__ float block_sum(float v, float* sh)
{
    #pragma unroll
    for (int o = 16; o; o >>= 1) v += __shfl_down_sync(0xffffffffu, v, o);
    int wid = threadIdx.x >> 5, lid = threadIdx.x & 31;
    if (lid == 0) sh[wid] = v;
    __syncthreads();
    if (wid == 0) {
        v = (lid < (RT >> 5)) ? sh[lid] : 0.0f;
        #pragma unroll
        for (int o = 4; o; o >>= 1) v += __shfl_down_sync(0xffffffffu, v, o);
    }
    return v;   // valid on thread 0
}

__global__ __launch_bounds__(RT) void recip_kernel(
    const float* __restrict__ R, const float* __restrict__ q,
    const float* __restrict__ kvecs, float* __restrict__ out)
{
    int m = blockIdx.x;
    int tid = threadIdx.x;
    int hk = blockIdx.y * RT + tid;

    float kvx = 0.f, kvy = 0.f, kvz = 0.f, w = 0.f;
    if (hk < g_nhalf) {
        int k = g_halfk[hk];
        float gx = kvecs[3 * k], gy = kvecs[3 * k + 1], gz = kvecs[3 * k + 2];
        const float* B = g_recip[m];
        kvx = gx * B[0] + gy * B[3] + gz * B[6];
        kvy = gx * B[1] + gy * B[4] + gz * B[7];
        kvz = gx * B[2] + gy * B[5] + gz * B[8];
        float ksq = kvx * kvx + kvy * kvy + kvz * kvz;
        w = 2.0f * expf(-0.25f * ksq / ALPHA) / ksq;   // x2: +-k symmetry
    }

    int s0 = g_start[m], s1 = g_start[m + 1];
    __shared__ float4 tile[RT];
    __shared__ float red[RT >> 5];

    float cr = 0.f, ci = 0.f, qq = 0.f;
    for (int base = s0; base < s1; base += RT) {
        int a = base + tid;
        if (a < s1) {
            float qa = q[a];
            tile[tid] = make_float4(R[3 * a], R[3 * a + 1], R[3 * a + 2], qa);
            qq += qa * qa;
        }
        __syncthreads();
        int cnt = min(RT, s1 - base);
        #pragma unroll 4
        for (int t = 0; t < cnt; t++) {
            float4 v = tile[t];
            float kdp = kvx * v.x + kvy * v.y + kvz * v.z;
            float s, c;
            __sincosf(kdp, &s, &c);
            cr = fmaf(v.w, c, cr);
            ci = fmaf(v.w, s, ci);
        }
        __syncthreads();
    }

    float part = (cr * cr + ci * ci) * w;
    part = block_sum(part, red);
    __syncthreads();
    float qqs = 0.f;
    if (blockIdx.y == 0) qqs = block_sum(qq, red);

    if (tid == 0) {
        float v = KE * g_pref[m] * part;
        if (blockIdx.y == 0)
            v -= KE * sqrtf(ALPHA / 3.14159265358979f) * qqs;
        atomicAdd(&out[m], v);
    }
}

// =====================================================================
extern "C" void kernel_launch(void* const* d_in, const int* in_sizes, int n_in,
                              void* d_out, int out_size)
{
    const float* q     = (const float*)d_in[0];      // partial_charges [A,1]
    const float* Rij   = (const float*)d_in[1];      // [P,3]
    const float* R     = (const float*)d_in[2];      // [A,3]
    const float* cell  = (const float*)d_in[3];      // [M,3,3]
    const float* kvecs = (const float*)d_in[4];      // [K,3]
    const int*   idx_m = (const int*)d_in[5];        // [A] int32
    const int*   idx_i = (const int*)d_in[6];        // [P] int32
    const int*   idx_j = (const int*)d_in[7];        // [P] int32
    float* out = (float*)d_out;

    int natoms = in_sizes[0];
    int npairs = in_sizes[1] / 3;
    int nk     = in_sizes[4] / 3;
    int nmol   = in_sizes[3] / 9;

    if (natoms > MAXA) natoms = MAXA;   // problem-fixed sizes; safety clamp

    int sblocks = (natoms + 255) / 256;
    if (sblocks < 1) sblocks = 1;
    setup_kernel<<<sblocks, 256>>>(q, cell, kvecs, idx_m, natoms, nk, out);

    real_kernel<<<1184, 256>>>(Rij, idx_i, idx_j, q, out, npairs);

    int nhalf_max = (nk + 1) / 2;
    int gy = (nhalf_max + RT - 1) / RT;
    dim3 grid(nmol, gy);
    recip_kernel<<<grid, RT>>>(R, q, kvecs, out);
}

// round 6
// speedup vs baseline: 1.9660x; 1.9660x over previous
#include <cuda_runtime.h>
#include <cuda_bf16.h>
#include <math.h>

#define KE       14.3996f
#define ALPHA    0.3f
#define CUTOFF   10.0f
#define NMOL     64
#define MAXA     100000
#define MAXK     1024
#define TWOPI    6.283185307179586f
#define SQA      0.5477225575051661f   /* sqrt(0.3) */

// -------- device scratch (no allocation allowed) --------
__device__ float  g_recip[NMOL][9];     // B[d][e] row-major: kv_e = sum_d g_d * B[d*3+e]
__device__ float  g_pref[NMOL];         // 2*pi / |det(cell)|
__device__ int    g_start[NMOL + 1];    // atom range per molecule (idx_m sorted)
__device__ int    g_halfk[MAXK];        // indices of half-space k vectors (any order)
__device__ int    g_nhalf;
__device__ float2 g_qmol[MAXA];         // {q, __int_as_float(mol)}

// =====================================================================
// Setup: zero out, per-molecule recip boxes, molecule offsets, half-k list
// (parallel compaction), packed (q, mol) array.  Indices are int32.
// =====================================================================
__global__ __launch_bounds__(256) void setup_kernel(
    const float* __restrict__ q, const float* __restrict__ cell,
    const float* __restrict__ kvecs, const int* __restrict__ idx_m,
    int natoms, int nk, float* __restrict__ out)
{
    int tid = threadIdx.x;
    if (blockIdx.x == 0) {
        __shared__ int cnt;
        if (tid == 0) cnt = 0;
        if (tid < NMOL) {
            // 3x3 inverse for cell m = tid
            const float* a = cell + 9 * tid;
            float a00 = a[0], a01 = a[1], a02 = a[2];
            float a10 = a[3], a11 = a[4], a12 = a[5];
            float a20 = a[6], a21 = a[7], a22 = a[8];
            float c00 = a11 * a22 - a12 * a21;
            float c01 = a02 * a21 - a01 * a22;
            float c02 = a01 * a12 - a02 * a11;
            float c10 = a12 * a20 - a10 * a22;
            float c11 = a00 * a22 - a02 * a20;
            float c12 = a02 * a10 - a00 * a12;
            float c20 = a10 * a21 - a11 * a20;
            float c21 = a01 * a20 - a00 * a21;
            float c22 = a00 * a11 - a01 * a10;
            float det = a00 * c00 + a01 * c10 + a02 * c20;
            float id = 1.0f / det;
            float i00 = c00 * id, i01 = c01 * id, i02 = c02 * id;
            float i10 = c10 * id, i11 = c11 * id, i12 = c12 * id;
            float i20 = c20 * id, i21 = c21 * id, i22 = c22 * id;
            // B[d*3+e] = 2*pi * inv[e][d]  (recip_box = 2*pi * inv(cell)^T)
            g_recip[tid][0] = TWOPI * i00;
            g_recip[tid][1] = TWOPI * i10;
            g_recip[tid][2] = TWOPI * i20;
            g_recip[tid][3] = TWOPI * i01;
            g_recip[tid][4] = TWOPI * i11;
            g_recip[tid][5] = TWOPI * i21;
            g_recip[tid][6] = TWOPI * i02;
            g_recip[tid][7] = TWOPI * i12;
            g_recip[tid][8] = TWOPI * i22;
            g_pref[tid] = TWOPI / fabsf(det);
            out[tid] = 0.0f;
        } else if (tid < 2 * NMOL + 1) {
            // lower_bound of m in sorted idx_m -> g_start[m]
            int m = tid - NMOL;
            int lo = 0, hi = natoms;
            while (lo < hi) {
                int mid = (lo + hi) >> 1;
                if (idx_m[mid] < m) lo = mid + 1; else hi = mid;
            }
            g_start[m] = lo;
        }
        __syncthreads();
        // parallel half-space k compaction (sign-symmetric set: one of {k,-k})
        for (int k = tid; k < nk; k += 256) {
            float gx = kvecs[3 * k], gy = kvecs[3 * k + 1], gz = kvecs[3 * k + 2];
            bool sel = (gz > 0.0f) ||
                       (gz == 0.0f && gy > 0.0f) ||
                       (gz == 0.0f && gy == 0.0f && gx > 0.0f);
            if (sel) {
                int p = atomicAdd(&cnt, 1);
                if (p < MAXK) g_halfk[p] = k;
            }
        }
        __syncthreads();
        if (tid == 0) g_nhalf = min(cnt, MAXK);
    }
    // pack (q, mol) for the real-space gather path
    for (int a = blockIdx.x * blockDim.x + tid; a < natoms; a += gridDim.x * blockDim.x) {
        int m = idx_m[a];
        g_qmol[a] = make_float2(q[a], __int_as_float(m));
    }
}

// =====================================================================
// Real space: grid-stride over pairs, shared per-molecule accumulators.
// =====================================================================
__global__ __launch_bounds__(256) void real_kernel(
    const float* __restrict__ Rij,
    const int* __restrict__ idx_i, const int* __restrict__ idx_j,
    const float* __restrict__ q, float* __restrict__ out, int npairs)
{
    __shared__ float acc[NMOL];
    int tid = threadIdx.x;
    if (tid < NMOL) acc[tid] = 0.0f;
    __syncthreads();

    const float frcut = erfcf(SQA * CUTOFF) / CUTOFF;
    const float cut2 = CUTOFF * CUTOFF;

    for (int p = blockIdx.x * blockDim.x + tid; p < npairs; p += gridDim.x * blockDim.x) {
        float x = Rij[3 * p], y = Rij[3 * p + 1], z = Rij[3 * p + 2];
        float d2 = x * x + y * y + z * z;
        if (d2 <= cut2) {
            int i = idx_i[p];
            int j = idx_j[p];
            float2 qm = __ldg(&g_qmol[i]);    // {q_i, mol bits} one 8B gather
            float qj = __ldg(&q[j]);
            float d = sqrtf(d2);
            float fr = erfcf(SQA * d) / d - frcut;
            float pot = qm.x * qj * fr;
            atomicAdd(&acc[__float_as_int(qm.y)], pot);
        }
    }
    __syncthreads();
    if (tid < NMOL) atomicAdd(&out[tid], 0.5f * KE * acc[tid]);
}

// =====================================================================
// Reciprocal space: block = (molecule, k-chunk), thread = one half-space k,
// loop over the molecule's atoms via shared float4 tiles. +- k symmetry => x2.
// Self-energy folded into blockIdx.y == 0 blocks.
// =====================================================================
#define RT 256

__device__ __forceinline__ float block_sum(float v, float* sh)
{
    #pragma unroll
    for (int o = 16; o; o >>= 1) v += __shfl_down_sync(0xffffffffu, v, o);
    int wid = threadIdx.x >> 5, lid = threadIdx.x & 31;
    if (lid == 0) sh[wid] = v;
    __syncthreads();
    if (wid == 0) {
        v = (lid < (RT >> 5)) ? sh[lid] : 0.0f;
        #pragma unroll
        for (int o = 4; o; o >>= 1) v += __shfl_down_sync(0xffffffffu, v, o);
    }
    return v;   // valid on thread 0
}

__global__ __launch_bounds__(RT) void recip_kernel(
    const float* __restrict__ R, const float* __restrict__ q,
    const float* __restrict__ kvecs, float* __restrict__ out)
{
    int m = blockIdx.x;
    int tid = threadIdx.x;
    int hk = blockIdx.y * RT + tid;

    float kvx = 0.f, kvy = 0.f, kvz = 0.f, w = 0.f;
    if (hk < g_nhalf) {
        int k = g_halfk[hk];
        float gx = kvecs[3 * k], gy = kvecs[3 * k + 1], gz = kvecs[3 * k + 2];
        const float* B = g_recip[m];
        kvx = gx * B[0] + gy * B[3] + gz * B[6];
        kvy = gx * B[1] + gy * B[4] + gz * B[7];
        kvz = gx * B[2] + gy * B[5] + gz * B[8];
        float ksq = kvx * kvx + kvy * kvy + kvz * kvz;
        w = 2.0f * expf(-0.25f * ksq / ALPHA) / ksq;   // x2: +-k symmetry
    }

    int s0 = g_start[m], s1 = g_start[m + 1];
    __shared__ float4 tile[RT];
    __shared__ float red[RT >> 5];

    float cr = 0.f, ci = 0.f, qq = 0.f;
    for (int base = s0; base < s1; base += RT) {
        int a = base + tid;
        if (a < s1) {
            float qa = q[a];
            tile[tid] = make_float4(R[3 * a], R[3 * a + 1], R[3 * a + 2], qa);
            qq += qa * qa;
        }
        __syncthreads();
        int cnt = min(RT, s1 - base);
        #pragma unroll 4
        for (int t = 0; t < cnt; t++) {
            float4 v = tile[t];
            float kdp = kvx * v.x + kvy * v.y + kvz * v.z;
            float s, c;
            __sincosf(kdp, &s, &c);
            cr = fmaf(v.w, c, cr);
            ci = fmaf(v.w, s, ci);
        }
        __syncthreads();
    }

    float part = (cr * cr + ci * ci) * w;
    part = block_sum(part, red);
    __syncthreads();
    float qqs = 0.f;
    if (blockIdx.y == 0) qqs = block_sum(qq, red);

    if (tid == 0) {
        float v = KE * g_pref[m] * part;
        if (blockIdx.y == 0)
            v -= KE * sqrtf(ALPHA / 3.14159265358979f) * qqs;
        atomicAdd(&out[m], v);
    }
}

// =====================================================================
extern "C" void kernel_launch(void* const* d_in, const int* in_sizes, int n_in,
                              void* d_out, int out_size)
{
    const float* q     = (const float*)d_in[0];      // partial_charges [A,1]
    const float* Rij   = (const float*)d_in[1];      // [P,3]
    const float* R     = (const float*)d_in[2];      // [A,3]
    const float* cell  = (const float*)d_in[3];      // [M,3,3]
    const float* kvecs = (const float*)d_in[4];      // [K,3]
    const int*   idx_m = (const int*)d_in[5];        // [A] int32
    const int*   idx_i = (const int*)d_in[6];        // [P] int32
    const int*   idx_j = (const int*)d_in[7];        // [P] int32
    float* out = (float*)d_out;

    int natoms = in_sizes[0];
    int npairs = in_sizes[1] / 3;
    int nk     = in_sizes[4] / 3;
    int nmol   = in_sizes[3] / 9;

    if (natoms > MAXA) natoms = MAXA;   // problem-fixed sizes; safety clamp

    int sblocks = (natoms + 255) / 256;
    if (sblocks < 1) sblocks = 1;
    setup_kernel<<<sblocks, 256>>>(q, cell, kvecs, idx_m, natoms, nk, out);

    int nhalf_max = (nk + 1) / 2;
    int gy = (nhalf_max + RT - 1) / RT;
    dim3 grid(nmol, gy);

    // One-time host resources for the capture-legal fork/join pattern.
    // (Created once; never destroyed during an active capture — destroying a
    //  forked stream mid-capture invalidates the capture.)
    static cudaStream_t s2 = nullptr;
    static cudaEvent_t  e1 = nullptr, e2 = nullptr;
    static bool init_ok = false;
    static bool init_tried = false;
    if (!init_tried) {
        init_tried = true;
        init_ok = (cudaStreamCreateWithFlags(&s2, cudaStreamNonBlocking) == cudaSuccess) &&
                  (cudaEventCreateWithFlags(&e1, cudaEventDisableTiming) == cudaSuccess) &&
                  (cudaEventCreateWithFlags(&e2, cudaEventDisableTiming) == cudaSuccess);
    }

    if (init_ok) {
        // fork: recip on s2 concurrently with real on the capture stream
        cudaEventRecord(e1, 0);
        cudaStreamWaitEvent(s2, e1, 0);
        recip_kernel<<<grid, RT, 0, s2>>>(R, q, kvecs, out);
        real_kernel<<<1184, 256>>>(Rij, idx_i, idx_j, q, out, npairs);
        cudaEventRecord(e2, s2);
        cudaStreamWaitEvent(0, e2, 0);   // join
    } else {
        real_kernel<<<1184, 256>>>(Rij, idx_i, idx_j, q, out, npairs);
        recip_kernel<<<grid, RT>>>(R, q, kvecs, out);
    }
}